// round 15
// baseline (speedup 1.0000x reference)
#include <cuda_runtime.h>
#include <math.h>

#define HID   2048
#define VOCAB 50257

#define GRU_NB    4096                 // split-K x2 gru blocks (2 per unit)
#define LROWS     16                   // rows per logits block (8 warps x 2)
#define LBLK      3142                 // ceil(VOCAB / LROWS) blocks per k-half
#define LOG_TOTAL (2 * LBLK)           // 6284 logits blocks
#define FIN_NB    148
#define FIN_ELEM  2                    // 148*256*2 = 75776 >= VOCAB

// Scratch (no cudaMalloc). Static zero-init; all counters self-reset.
__device__ float        g_part[2][6][HID];   // gru split-K partials
__device__ unsigned int g_unit_cnt[HID];     // per-unit arrival counters
__device__ float        g_hnew[HID];
__device__ float        g_lpart[2][VOCAB];   // logits k-half partials
__device__ unsigned int g_row_cnt[VOCAB];    // per-row arrival counters
__device__ float        g_logits[VOCAB];
__device__ float        g_sum;
__device__ unsigned int g_gruA, g_gruB;      // completed units <1024 / >=1024
__device__ unsigned int g_logcnt;            // finished logits blocks
__device__ unsigned int g_fincnt;            // finished finalize blocks

__global__ void __launch_bounds__(256, 6) fused_kernel(
    const int*   __restrict__ idx,
    const float* __restrict__ hidden,
    const float* __restrict__ embed,
    const float* __restrict__ w_ih,
    const float* __restrict__ w_hh,
    const float* __restrict__ b_ih,
    const float* __restrict__ b_hh,
    const float* __restrict__ w_out,
    const float* __restrict__ b_out,
    float*       __restrict__ out,
    float*       __restrict__ hnew_out)   // may be null
{
    const int tid  = threadIdx.x;
    const int lane = tid & 31;
    const int warp = tid >> 5;
    const int bid  = blockIdx.x;

    // ======================= GRU blocks (bids 0..4095) ====================
    if (bid < GRU_NB) {
        const int u    = bid >> 1;
        const int half = bid & 1;
        const int token = idx[0];
        const int k = half * 256 + tid;

        const float4 xv   = ((const float4*)(embed + (size_t)token * HID))[k];
        const float4 hv   = ((const float4*)hidden)[k];
        const float4 wi_r = ((const float4*)(w_ih + (size_t)( u         ) * HID))[k];
        const float4 wi_z = ((const float4*)(w_ih + (size_t)( HID   + u ) * HID))[k];
        const float4 wi_n = ((const float4*)(w_ih + (size_t)( 2*HID + u ) * HID))[k];
        const float4 wh_r = ((const float4*)(w_hh + (size_t)( u         ) * HID))[k];
        const float4 wh_z = ((const float4*)(w_hh + (size_t)( HID   + u ) * HID))[k];
        const float4 wh_n = ((const float4*)(w_hh + (size_t)( 2*HID + u ) * HID))[k];

        float a[6];
        a[0] = wi_r.x*xv.x + wi_r.y*xv.y + wi_r.z*xv.z + wi_r.w*xv.w;
        a[1] = wi_z.x*xv.x + wi_z.y*xv.y + wi_z.z*xv.z + wi_z.w*xv.w;
        a[2] = wi_n.x*xv.x + wi_n.y*xv.y + wi_n.z*xv.z + wi_n.w*xv.w;
        a[3] = wh_r.x*hv.x + wh_r.y*hv.y + wh_r.z*hv.z + wh_r.w*hv.w;
        a[4] = wh_z.x*hv.x + wh_z.y*hv.y + wh_z.z*hv.z + wh_z.w*hv.w;
        a[5] = wh_n.x*hv.x + wh_n.y*hv.y + wh_n.z*hv.z + wh_n.w*hv.w;

        #pragma unroll
        for (int o = 16; o; o >>= 1) {
            #pragma unroll
            for (int j = 0; j < 6; j++)
                a[j] += __shfl_xor_sync(0xffffffffu, a[j], o);
        }

        __shared__ float s[8][6];
        if (lane == 0) {
            #pragma unroll
            for (int j = 0; j < 6; j++) s[warp][j] = a[j];
        }
        __syncthreads();

        if (tid == 0) {
            float t[6];
            #pragma unroll
            for (int j = 0; j < 6; j++) {
                float v = s[0][j];
                #pragma unroll
                for (int w = 1; w < 8; w++) v += s[w][j];
                t[j] = v;
            }
            #pragma unroll
            for (int j = 0; j < 6; j++) g_part[half][j][u] = t[j];
            __threadfence();
            const unsigned int prev = atomicAdd(&g_unit_cnt[u], 1u);

            if (prev == 1u) {                    // second arriver combines
                __threadfence();
                const int oh = 1 - half;
                const float gir = t[0] + g_part[oh][0][u] + b_ih[u];
                const float giz = t[1] + g_part[oh][1][u] + b_ih[HID + u];
                const float gin = t[2] + g_part[oh][2][u] + b_ih[2*HID + u];
                const float ghr = t[3] + g_part[oh][3][u] + b_hh[u];
                const float ghz = t[4] + g_part[oh][4][u] + b_hh[HID + u];
                const float ghn = t[5] + g_part[oh][5][u] + b_hh[2*HID + u];

                const float r  = 1.0f / (1.0f + expf(-(gir + ghr)));
                const float z  = 1.0f / (1.0f + expf(-(giz + ghz)));
                const float n  = tanhf(gin + r * ghn);
                const float hn = (1.0f - z) * n + z * hidden[u];

                g_hnew[u] = hn;
                if (hnew_out) hnew_out[u] = hn;
                g_unit_cnt[u] = 0u;              // reset for next replay
                __threadfence();                 // release h_new
                atomicAdd(u < HID/2 ? &g_gruA : &g_gruB, 1u);
            }
        }
        return;
    }

    // ==================== Logits blocks (split-K x2) ======================
    if (bid < GRU_NB + LOG_TOTAL) {
        const int lbid = bid - GRU_NB;
        const int half = (lbid >= LBLK) ? 1 : 0;
        const int blk  = half ? (lbid - LBLK) : lbid;

        // Wait for our k-half of h_new (producers all have lower bids).
        if (tid == 0) {
            volatile unsigned int* f = half ? &g_gruB : &g_gruA;
            while (*f < (unsigned int)(HID/2)) { __nanosleep(64); }
            __threadfence();                     // acquire h_new
        }
        __syncthreads();

        const int r0 = blk * LROWS + warp * 2;
        const int r1 = r0 + 1;
        const float4* h4 = ((const float4*)g_hnew) + half * 256;

        float acc0 = 0.0f, acc1 = 0.0f;
        if (r0 < VOCAB) {
            const float4* w4 = (const float4*)(w_out + (size_t)r0 * HID) + half * 256;
            #pragma unroll
            for (int j = 0; j < 8; j++) {
                const int k = lane + 32 * j;
                const float4 w = w4[k];
                const float4 h = h4[k];
                acc0 += w.x*h.x + w.y*h.y + w.z*h.z + w.w*h.w;
            }
        }
        if (r1 < VOCAB) {
            const float4* w4 = (const float4*)(w_out + (size_t)r1 * HID) + half * 256;
            #pragma unroll
            for (int j = 0; j < 8; j++) {
                const int k = lane + 32 * j;
                const float4 w = w4[k];
                const float4 h = h4[k];
                acc1 += w.x*h.x + w.y*h.y + w.z*h.z + w.w*h.w;
            }
        }
        #pragma unroll
        for (int o = 16; o; o >>= 1) {
            acc0 += __shfl_xor_sync(0xffffffffu, acc0, o);
            acc1 += __shfl_xor_sync(0xffffffffu, acc1, o);
        }

        __shared__ float s_exp[8];
        float e = 0.0f;
        if (lane == 0) {
            if (r0 < VOCAB) g_lpart[half][r0] = acc0;
            if (r1 < VOCAB) g_lpart[half][r1] = acc1;
            __threadfence();                     // release partials
            bool win0 = false, win1 = false;
            if (r0 < VOCAB) win0 = (atomicAdd(&g_row_cnt[r0], 1u) == 1u);
            if (r1 < VOCAB) win1 = (atomicAdd(&g_row_cnt[r1], 1u) == 1u);
            if (win0 | win1) __threadfence();    // acquire partner partials
            if (win0) {
                const float l = fmaxf(acc0 + g_lpart[1-half][r0] + b_out[r0], 0.0f);
                g_logits[r0] = l;
                e += expf(l);
                g_row_cnt[r0] = 0u;              // reset for next replay
            }
            if (win1) {
                const float l = fmaxf(acc1 + g_lpart[1-half][r1] + b_out[r1], 0.0f);
                g_logits[r1] = l;
                e += expf(l);
                g_row_cnt[r1] = 0u;
            }
            s_exp[warp] = e;
        }
        __syncthreads();
        if (tid == 0) {
            float t = s_exp[0];
            #pragma unroll
            for (int w = 1; w < 8; w++) t += s_exp[w];
            if (t != 0.0f) atomicAdd(&g_sum, t);
            __threadfence();                     // release g_sum/g_logits
            atomicAdd(&g_logcnt, 1u);
        }
        return;
    }

    // ======================= Finalize blocks ==============================
    {
        const int fbid = bid - (GRU_NB + LOG_TOTAL);
        __shared__ float s_ls;
        if (tid == 0) {
            volatile unsigned int* c = &g_logcnt;
            while (*c < (unsigned int)LOG_TOTAL) { __nanosleep(64); }
            __threadfence();                     // acquire g_sum/g_logits
            s_ls = logf(g_sum);
        }
        __syncthreads();

        const float logsum = s_ls;
        #pragma unroll
        for (int j = 0; j < FIN_ELEM; j++) {
            const int v = fbid * 256 + tid + j * FIN_NB * 256;
            if (v < VOCAB)
                out[v] = g_logits[v] - logsum;
        }

        __syncthreads();
        if (tid == 0) {
            if (atomicAdd(&g_fincnt, 1u) == FIN_NB - 1u) {
                // last finalizer resets shared counters for next graph replay
                g_fincnt = 0u;
                g_logcnt = 0u;
                g_gruA   = 0u;
                g_gruB   = 0u;
                g_sum    = 0.0f;
            }
        }
    }
}

// ---------------------------------------------------------------------------
extern "C" void kernel_launch(void* const* d_in, const int* in_sizes, int n_in,
                              void* d_out, int out_size)
{
    const int*   idx    = (const int*)  d_in[0];
    const float* hidden = (const float*)d_in[1];
    const float* embed  = (const float*)d_in[2];
    const float* w_ih   = (const float*)d_in[3];
    const float* w_hh   = (const float*)d_in[4];
    const float* b_ih   = (const float*)d_in[5];
    const float* b_hh   = (const float*)d_in[6];
    const float* w_out  = (const float*)d_in[7];
    const float* b_out  = (const float*)d_in[8];

    float* out = (float*)d_out;
    float* hnew_out = (out_size >= VOCAB + HID) ? (out + VOCAB) : nullptr;

    fused_kernel<<<GRU_NB + LOG_TOTAL + FIN_NB, 256>>>(
        idx, hidden, embed, w_ih, w_hh, b_ih, b_hh, w_out, b_out,
        out, hnew_out);
}

// round 16
// speedup vs baseline: 1.1134x; 1.1134x over previous
#include <cuda_runtime.h>
#include <math.h>

#define HID   2048
#define VOCAB 50257

#define GRU_NB   4096                    // split-K x2 gru blocks (2 per unit)
#define LOG_NB   ((VOCAB + 7) / 8)       // 6283 logits blocks, 8 rows each
#define FIN_NB   148

// Scratch (no cudaMalloc). Static zero-init; all counters self-reset.
__device__ float        g_part[2][6][HID];   // gru split-K partials
__device__ unsigned int g_unit_cnt[HID];     // per-unit arrival counters
__device__ float        g_hnew[HID];
__device__ float        g_logits[VOCAB];
__device__ float        g_sum;
__device__ unsigned int g_gruDone;           // completed hidden units (0..2048)
__device__ unsigned int g_logcnt;            // finished logits blocks
__device__ unsigned int g_fincnt;            // finished finalize blocks

__global__ void __launch_bounds__(256, 6) fused_kernel(
    const int*   __restrict__ idx,
    const float* __restrict__ hidden,
    const float* __restrict__ embed,
    const float* __restrict__ w_ih,
    const float* __restrict__ w_hh,
    const float* __restrict__ b_ih,
    const float* __restrict__ b_hh,
    const float* __restrict__ w_out,
    const float* __restrict__ b_out,
    float*       __restrict__ out,
    float*       __restrict__ hnew_out)   // may be null
{
    const int tid  = threadIdx.x;
    const int lane = tid & 31;
    const int warp = tid >> 5;
    const int bid  = blockIdx.x;

    // ======================= GRU blocks (bids 0..4095) ====================
    if (bid < GRU_NB) {
        const int u     = bid >> 1;
        const int half  = bid & 1;
        const int token = idx[0];
        const int k     = half * 256 + tid;

        const float4 xv   = ((const float4*)(embed + (size_t)token * HID))[k];
        const float4 hv   = ((const float4*)hidden)[k];
        const float4 wi_r = ((const float4*)(w_ih + (size_t)( u         ) * HID))[k];
        const float4 wi_z = ((const float4*)(w_ih + (size_t)( HID   + u ) * HID))[k];
        const float4 wi_n = ((const float4*)(w_ih + (size_t)( 2*HID + u ) * HID))[k];
        const float4 wh_r = ((const float4*)(w_hh + (size_t)( u         ) * HID))[k];
        const float4 wh_z = ((const float4*)(w_hh + (size_t)( HID   + u ) * HID))[k];
        const float4 wh_n = ((const float4*)(w_hh + (size_t)( 2*HID + u ) * HID))[k];

        float a[6];
        a[0] = wi_r.x*xv.x + wi_r.y*xv.y + wi_r.z*xv.z + wi_r.w*xv.w;
        a[1] = wi_z.x*xv.x + wi_z.y*xv.y + wi_z.z*xv.z + wi_z.w*xv.w;
        a[2] = wi_n.x*xv.x + wi_n.y*xv.y + wi_n.z*xv.z + wi_n.w*xv.w;
        a[3] = wh_r.x*hv.x + wh_r.y*hv.y + wh_r.z*hv.z + wh_r.w*hv.w;
        a[4] = wh_z.x*hv.x + wh_z.y*hv.y + wh_z.z*hv.z + wh_z.w*hv.w;
        a[5] = wh_n.x*hv.x + wh_n.y*hv.y + wh_n.z*hv.z + wh_n.w*hv.w;

        #pragma unroll
        for (int o = 16; o; o >>= 1) {
            #pragma unroll
            for (int j = 0; j < 6; j++)
                a[j] += __shfl_xor_sync(0xffffffffu, a[j], o);
        }

        __shared__ float s[8][6];
        if (lane == 0) {
            #pragma unroll
            for (int j = 0; j < 6; j++) s[warp][j] = a[j];
        }
        __syncthreads();

        if (tid == 0) {
            float t[6];
            #pragma unroll
            for (int j = 0; j < 6; j++) {
                float v = s[0][j];
                #pragma unroll
                for (int w = 1; w < 8; w++) v += s[w][j];
                t[j] = v;
            }
            #pragma unroll
            for (int j = 0; j < 6; j++) g_part[half][j][u] = t[j];
            __threadfence();
            const unsigned int prev = atomicAdd(&g_unit_cnt[u], 1u);

            if (prev == 1u) {                    // second arriver combines
                __threadfence();
                const int oh = 1 - half;
                const float gir = t[0] + g_part[oh][0][u] + b_ih[u];
                const float giz = t[1] + g_part[oh][1][u] + b_ih[HID + u];
                const float gin = t[2] + g_part[oh][2][u] + b_ih[2*HID + u];
                const float ghr = t[3] + g_part[oh][3][u] + b_hh[u];
                const float ghz = t[4] + g_part[oh][4][u] + b_hh[HID + u];
                const float ghn = t[5] + g_part[oh][5][u] + b_hh[2*HID + u];

                const float r  = 1.0f / (1.0f + expf(-(gir + ghr)));
                const float z  = 1.0f / (1.0f + expf(-(giz + ghz)));
                const float n  = tanhf(gin + r * ghn);
                const float hn = (1.0f - z) * n + z * hidden[u];

                g_hnew[u] = hn;
                if (hnew_out) hnew_out[u] = hn;
                g_unit_cnt[u] = 0u;              // reset for next replay
                __threadfence();                 // release h_new
                atomicAdd(&g_gruDone, 1u);
            }
        }
        return;
    }

    // ================= Logits blocks (proven warp-per-row) ================
    if (bid < GRU_NB + LOG_NB) {
        // One-time wait for h_new (producers all have lower bids -> safe).
        if (tid == 0) {
            volatile unsigned int* f = &g_gruDone;
            while (*f < (unsigned int)HID) { __nanosleep(64); }
            __threadfence();                     // acquire h_new
        }
        __syncthreads();

        const int row = (bid - GRU_NB) * 8 + warp;

        float e = 0.0f;                  // this warp's exp(l), 0 if row invalid
        if (row < VOCAB) {
            const float4* w4 = (const float4*)(w_out + (size_t)row * HID);
            const float4* h4 = (const float4*)g_hnew;
            float acc = 0.0f;
            #pragma unroll
            for (int j = 0; j < 16; j++) {
                const int k = lane + 32 * j;
                const float4 w = w4[k];
                const float4 h = h4[k];
                acc += w.x*h.x + w.y*h.y + w.z*h.z + w.w*h.w;
            }
            #pragma unroll
            for (int o = 16; o; o >>= 1)
                acc += __shfl_xor_sync(0xffffffffu, acc, o);
            if (lane == 0) {
                const float l = fmaxf(acc + b_out[row], 0.0f);
                g_logits[row] = l;               // no max pass: l in [0, ~6]
                e = expf(l);
            }
        }

        __shared__ float s_exp[8];
        if (lane == 0) s_exp[warp] = e;
        __syncthreads();
        if (tid == 0) {
            float t = s_exp[0];
            #pragma unroll
            for (int w = 1; w < 8; w++) t += s_exp[w];
            atomicAdd(&g_sum, t);
            __threadfence();                     // release g_sum + g_logits
            atomicAdd(&g_logcnt, 1u);
        }
        return;
    }

    // ======================= Finalize blocks ==============================
    {
        const int fbid = bid - (GRU_NB + LOG_NB);
        __shared__ float s_ls;
        if (tid == 0) {
            volatile unsigned int* c = &g_logcnt;
            while (*c < (unsigned int)LOG_NB) { __nanosleep(64); }
            __threadfence();                     // acquire g_sum / g_logits
            s_ls = logf(g_sum);
        }
        __syncthreads();

        const float logsum = s_ls;
        #pragma unroll
        for (int j = 0; j < 2; j++) {
            const int v = fbid * 256 + tid + j * FIN_NB * 256;
            if (v < VOCAB)
                out[v] = g_logits[v] - logsum;
        }

        __syncthreads();
        if (tid == 0) {
            if (atomicAdd(&g_fincnt, 1u) == FIN_NB - 1u) {
                // last finalizer resets shared state for the next graph replay
                g_fincnt  = 0u;
                g_logcnt  = 0u;
                g_gruDone = 0u;
                g_sum     = 0.0f;
            }
        }
    }
}

// ---------------------------------------------------------------------------
extern "C" void kernel_launch(void* const* d_in, const int* in_sizes, int n_in,
                              void* d_out, int out_size)
{
    const int*   idx    = (const int*)  d_in[0];
    const float* hidden = (const float*)d_in[1];
    const float* embed  = (const float*)d_in[2];
    const float* w_ih   = (const float*)d_in[3];
    const float* w_hh   = (const float*)d_in[4];
    const float* b_ih   = (const float*)d_in[5];
    const float* b_hh   = (const float*)d_in[6];
    const float* w_out  = (const float*)d_in[7];
    const float* b_out  = (const float*)d_in[8];

    float* out = (float*)d_out;
    float* hnew_out = (out_size >= VOCAB + HID) ? (out + VOCAB) : nullptr;

    fused_kernel<<<GRU_NB + LOG_NB + FIN_NB, 256>>>(
        idx, hidden, embed, w_ih, w_hh, b_ih, b_hh, w_out, b_out,
        out, hnew_out);
}

// round 17
// speedup vs baseline: 1.1910x; 1.0697x over previous
#include <cuda_runtime.h>
#include <math.h>

#define HID   2048
#define VOCAB 50257

#define ROW_BYTES   (HID * 4)            // 8192 B per weight row
#define SMEM_WEIGHTS (6 * ROW_BYTES)     // 49152 B dynamic smem

// Scratch (no cudaMalloc allowed).
__device__ float        g_hnew[HID];
__device__ float        g_logits[VOCAB];
__device__ unsigned int g_max_u;
__device__ float        g_sum;
__device__ unsigned int g_count;         // softmax completion counter

// ---------------------------------------------------------------------------
// Kernel 1: GRU cell, block-per-unit, weights fetched by TMA bulk copy.
// One thread issues six 8KB cp.async.bulk transfers (w_ih/w_hh rows u, H+u,
// 2H+u) into smem; the TMA engine streams them at LTS-cap rate, decoupled
// from warp latency. All threads then compute the 6 dots from smem.
// ---------------------------------------------------------------------------
__global__ void __launch_bounds__(256) gru_kernel(
    const int*   __restrict__ idx,
    const float* __restrict__ hidden,
    const float* __restrict__ embed,
    const float* __restrict__ w_ih,
    const float* __restrict__ w_hh,
    const float* __restrict__ b_ih,
    const float* __restrict__ b_hh,
    float*       __restrict__ hnew_out)   // may be null
{
    extern __shared__ float sw[];          // 6 rows x 2048 floats
    __shared__ __align__(8) unsigned long long s_mbar;
    __shared__ float s_red[8][6];

    const int tid  = threadIdx.x;
    const int lane = tid & 31;
    const int warp = tid >> 5;
    const int u    = blockIdx.x;

    const unsigned int mbar = (unsigned int)__cvta_generic_to_shared(&s_mbar);
    const unsigned int swem = (unsigned int)__cvta_generic_to_shared(sw);

    if (tid == 0) {
        asm volatile("mbarrier.init.shared.b64 [%0], 1;" :: "r"(mbar) : "memory");
        asm volatile("mbarrier.arrive.expect_tx.shared.b64 _, [%0], %1;"
                     :: "r"(mbar), "r"((unsigned)SMEM_WEIGHTS) : "memory");
        const float* srcs[6] = {
            w_ih + (size_t)( u         ) * HID,
            w_ih + (size_t)( HID   + u ) * HID,
            w_ih + (size_t)( 2*HID + u ) * HID,
            w_hh + (size_t)( u         ) * HID,
            w_hh + (size_t)( HID   + u ) * HID,
            w_hh + (size_t)( 2*HID + u ) * HID };
        #pragma unroll
        for (int j = 0; j < 6; j++) {
            asm volatile(
                "cp.async.bulk.shared::cta.global.mbarrier::complete_tx::bytes"
                " [%0], [%1], %2, [%3];"
                :: "r"(swem + j * ROW_BYTES), "l"(srcs[j]),
                   "r"((unsigned)ROW_BYTES), "r"(mbar) : "memory");
        }
    }
    __syncthreads();   // make mbarrier init visible to all waiters

    // Load x/h while TMA streams weights (overlap).
    const int token = idx[0];
    const float4* x4 = (const float4*)(embed + (size_t)token * HID);
    const float4* h4 = (const float4*)hidden;
    float4 xv[2], hv[2];
    xv[0] = x4[tid];       xv[1] = x4[tid + 256];
    hv[0] = h4[tid];       hv[1] = h4[tid + 256];

    // Wait for all six rows (phase 0).
    {
        unsigned int done;
        asm volatile(
            "{\n\t.reg .pred p;\n\t"
            "mbarrier.try_wait.parity.shared.b64 p, [%1], 0;\n\t"
            "selp.b32 %0, 1, 0, p;\n\t}"
            : "=r"(done) : "r"(mbar) : "memory");
        while (!done) {
            asm volatile(
                "{\n\t.reg .pred p;\n\t"
                "mbarrier.try_wait.parity.shared.b64 p, [%1], 0, 0x989680;\n\t"
                "selp.b32 %0, 1, 0, p;\n\t}"
                : "=r"(done) : "r"(mbar) : "memory");
        }
    }

    // 6 dot products from smem (conflict-free: consecutive threads ->
    // consecutive 16B).
    float a[6] = {0.f, 0.f, 0.f, 0.f, 0.f, 0.f};
    #pragma unroll
    for (int j = 0; j < 2; j++) {
        const int k = tid + j * 256;
        const float4 x = xv[j];
        const float4 h = hv[j];
        #pragma unroll
        for (int r = 0; r < 6; r++) {
            const float4 w = ((const float4*)(sw + r * HID))[k];
            const float4 v = (r < 3) ? x : h;
            a[r] += w.x*v.x + w.y*v.y + w.z*v.z + w.w*v.w;
        }
    }

    #pragma unroll
    for (int o = 16; o; o >>= 1) {
        #pragma unroll
        for (int j = 0; j < 6; j++)
            a[j] += __shfl_xor_sync(0xffffffffu, a[j], o);
    }
    if (lane == 0) {
        #pragma unroll
        for (int j = 0; j < 6; j++) s_red[warp][j] = a[j];
    }
    __syncthreads();

    if (tid == 0) {
        float t[6];
        #pragma unroll
        for (int j = 0; j < 6; j++) {
            float v = s_red[0][j];
            #pragma unroll
            for (int w = 1; w < 8; w++) v += s_red[w][j];
            t[j] = v;
        }
        const float gir = t[0] + b_ih[u];
        const float giz = t[1] + b_ih[HID + u];
        const float gin = t[2] + b_ih[2*HID + u];
        const float ghr = t[3] + b_hh[u];
        const float ghz = t[4] + b_hh[HID + u];
        const float ghn = t[5] + b_hh[2*HID + u];

        const float r  = 1.0f / (1.0f + expf(-(gir + ghr)));
        const float z  = 1.0f / (1.0f + expf(-(giz + ghz)));
        const float n  = tanhf(gin + r * ghn);
        const float hn = (1.0f - z) * n + z * hidden[u];

        g_hnew[u] = hn;
        if (hnew_out) hnew_out[u] = hn;
        if (u == 0) { g_max_u = 0u; g_sum = 0.0f; g_count = 0u; }

        asm volatile("mbarrier.inval.shared.b64 [%0];" :: "r"(mbar) : "memory");
    }
}

// ---------------------------------------------------------------------------
// Kernel 2: logits = relu(w_out @ h_new + b_out). Warp-per-row, 8 rows/block
// (R9 exact: measured ~87% of HBM).
// ---------------------------------------------------------------------------
__global__ void __launch_bounds__(256) logits_kernel(
    const float* __restrict__ w_out,
    const float* __restrict__ b_out)
{
    const int lane = threadIdx.x & 31;
    const int warp = threadIdx.x >> 5;
    const int row  = blockIdx.x * 8 + warp;

    float l = 0.0f;
    if (row < VOCAB) {
        const float4* w4 = (const float4*)(w_out + (size_t)row * HID);
        const float4* h4 = (const float4*)g_hnew;
        float acc = 0.0f;
        #pragma unroll
        for (int j = 0; j < 16; j++) {
            const int k = lane + 32 * j;
            const float4 w = w4[k];
            const float4 h = h4[k];
            acc += w.x*h.x + w.y*h.y + w.z*h.z + w.w*h.w;
        }
        #pragma unroll
        for (int o = 16; o; o >>= 1)
            acc += __shfl_xor_sync(0xffffffffu, acc, o);
        l = fmaxf(acc + b_out[row], 0.0f);
        if (lane == 0) g_logits[row] = l;
    }

    __shared__ float smax[8];
    if (lane == 0) smax[warp] = l;
    __syncthreads();
    if (threadIdx.x == 0) {
        float m = smax[0];
        #pragma unroll
        for (int w = 1; w < 8; w++) m = fmaxf(m, smax[w]);
        atomicMax(&g_max_u, __float_as_uint(m));   // all values >= 0
    }
}

// ---------------------------------------------------------------------------
// Kernel 3: fused sum-exp + finalize (R9 exact). ONE wave, co-resident spin.
// ---------------------------------------------------------------------------
#define NBLK 148
#define ELEMS_PER_THREAD 2

__global__ void __launch_bounds__(256) softmax_kernel(float* __restrict__ out)
{
    const int tid    = threadIdx.x;
    const int stride = NBLK * 256;
    const float m    = __uint_as_float(g_max_u);

    float lv[ELEMS_PER_THREAD];
    int   vi[ELEMS_PER_THREAD];
    float s = 0.0f;

    #pragma unroll
    for (int j = 0; j < ELEMS_PER_THREAD; j++) {
        const int v = blockIdx.x * 256 + tid + j * stride;
        vi[j] = v;
        if (v < VOCAB) {
            const float l = g_logits[v];
            lv[j] = l;
            s += expf(l - m);
        }
    }

    #pragma unroll
    for (int o = 16; o; o >>= 1)
        s += __shfl_xor_sync(0xffffffffu, s, o);

    __shared__ float sh[8];
    const int lane = tid & 31;
    const int warp = tid >> 5;
    if (lane == 0) sh[warp] = s;
    __syncthreads();

    if (tid == 0) {
        float t = sh[0];
        #pragma unroll
        for (int w = 1; w < 8; w++) t += sh[w];
        atomicAdd(&g_sum, t);
        __threadfence();
        atomicAdd(&g_count, 1u);
        volatile unsigned int* cnt = &g_count;
        while (*cnt < (unsigned int)gridDim.x) { __nanosleep(64); }
        __threadfence();
        sh[0] = logf(g_sum);
    }
    __syncthreads();

    const float logsum = sh[0];
    #pragma unroll
    for (int j = 0; j < ELEMS_PER_THREAD; j++) {
        if (vi[j] < VOCAB)
            out[vi[j]] = lv[j] - m - logsum;
    }
}

// ---------------------------------------------------------------------------
extern "C" void kernel_launch(void* const* d_in, const int* in_sizes, int n_in,
                              void* d_out, int out_size)
{
    const int*   idx    = (const int*)  d_in[0];
    const float* hidden = (const float*)d_in[1];
    const float* embed  = (const float*)d_in[2];
    const float* w_ih   = (const float*)d_in[3];
    const float* w_hh   = (const float*)d_in[4];
    const float* b_ih   = (const float*)d_in[5];
    const float* b_hh   = (const float*)d_in[6];
    const float* w_out  = (const float*)d_in[7];
    const float* b_out  = (const float*)d_in[8];

    float* out = (float*)d_out;
    float* hnew_out = (out_size >= VOCAB + HID) ? (out + VOCAB) : nullptr;

    static int attr_done = 0;
    if (!attr_done) {
        cudaFuncSetAttribute(gru_kernel,
                             cudaFuncAttributeMaxDynamicSharedMemorySize,
                             SMEM_WEIGHTS);
        attr_done = 1;
    }

    gru_kernel<<<HID, 256, SMEM_WEIGHTS>>>(idx, hidden, embed, w_ih, w_hh,
                                           b_ih, b_hh, hnew_out);
    logits_kernel<<<(VOCAB + 7) / 8, 256>>>(w_out, b_out);
    softmax_kernel<<<NBLK, 256>>>(out);
}